// round 8
// baseline (speedup 1.0000x reference)
#include <cuda_runtime.h>
#include <cuda_fp16.h>
#include <cstdint>

#define BB 4
#define SS 1024
#define DD 1024
#define HH 16
#define HDIM 64
#define NBH (BB*HH)

// fp16 scratch (allocation-free)
__device__ __align__(16) __half g_q16 [BB*SS*DD];
__device__ __align__(16) __half g_k16 [BB*SS*DD];
__device__ __align__(16) __half g_v16 [BB*SS*DD];
__device__ __align__(16) __half g_wq16[DD*DD];
__device__ __align__(16) __half g_wk16[DD*DD];
__device__ __align__(16) __half g_wv16[DD*DD];
__device__ __align__(16) __half g_wo16[DD*DD];
__device__ __align__(16) __half g_qh16[NBH*SS*HDIM];   // [bh][q][d]
__device__ __align__(16) __half g_kh16[NBH*SS*HDIM];   // [bh][key][d]
__device__ __align__(16) __half g_vht16[NBH*SS*HDIM];  // [bh][d][key]  TRANSPOSED
__device__ __align__(16) __half g_y16 [NBH*SS*HDIM];   // [bh][q][d]

#define MMA_F16(acc, a0,a1,a2,a3, b0,b1)                                    \
    asm volatile(                                                           \
        "mma.sync.aligned.m16n8k16.row.col.f32.f16.f16.f32 "                \
        "{%0,%1,%2,%3}, {%4,%5,%6,%7}, {%8,%9}, {%0,%1,%2,%3};"             \
        : "+f"(acc[0]), "+f"(acc[1]), "+f"(acc[2]), "+f"(acc[3])            \
        : "r"(a0), "r"(a1), "r"(a2), "r"(a3), "r"(b0), "r"(b1))

__device__ __forceinline__ void ldmx4(uint32_t& r0, uint32_t& r1,
                                      uint32_t& r2, uint32_t& r3, uint32_t addr) {
    asm volatile("ldmatrix.sync.aligned.m8n8.x4.shared.b16 {%0,%1,%2,%3}, [%4];"
                 : "=r"(r0), "=r"(r1), "=r"(r2), "=r"(r3) : "r"(addr));
}

// ---------------------------------------------------------------------------
// Fused fp32 -> fp16 conversion for 7 tensors in one launch.
// ---------------------------------------------------------------------------
struct CvtArgs {
    const float* src[7];
    __half*      dst[7];
    int          n[7];
};

__global__ void __launch_bounds__(256) convert_all(CvtArgs args) {
    const int t = blockIdx.y;
    const int n = args.n[t];
    int base = (blockIdx.x * 256 + threadIdx.x) * 8;
    if (base >= n) return;
    const float4* s = (const float4*)(args.src[t] + base);
    float4 f0 = s[0], f1 = s[1];
    __half2 h0 = __floats2half2_rn(f0.x, f0.y);
    __half2 h1 = __floats2half2_rn(f0.z, f0.w);
    __half2 h2 = __floats2half2_rn(f1.x, f1.y);
    __half2 h3 = __floats2half2_rn(f1.z, f1.w);
    uint4 o;
    o.x = *(uint32_t*)&h0; o.y = *(uint32_t*)&h1;
    o.z = *(uint32_t*)&h2; o.w = *(uint32_t*)&h3;
    *(uint4*)(args.dst[t] + base) = o;
}

// ---------------------------------------------------------------------------
// FP16 tensor-core GEMM + bias + ReLU.
// C[m][n] = relu(sum_k A[m][k]*W[n][k] + bias[n])
// CTA tile 128x128, 128 threads / 4 warps (2x2), warp tile 64x64, m16n8k16.
// 3-stage cp.async smem pipeline + double-buffered ldmatrix fragments.
// ---------------------------------------------------------------------------
#define GBK 64
#define HST 72
#define HTILE (128*HST)                 // halves per matrix per stage
#define STAGEH (2*HTILE)                // halves per stage (A+W)
#define GEMM_SMEM (3*STAGEH*2)          // 110592 bytes

struct QKVArgs {
    const __half* A[3];
    const __half* W[3];
    const float*  b[3];
    __half*       C[3];
};

struct GemmCore {
    uint32_t smem_base;
    int tid, lane, warp, wm, wn, lr, lc, bm, bn;
    int aRow, aCol, bRow, bCol;

    __device__ __forceinline__ void init(uint32_t sb) {
        smem_base = sb;
        tid  = threadIdx.x;
        lane = tid & 31;
        warp = tid >> 5;
        wm   = warp >> 1;               // 2 warps along M
        wn   = warp & 1;                // 2 warps along N
        lr   = lane >> 2;
        lc   = lane & 3;
        bm   = blockIdx.y * 128;
        bn   = blockIdx.x * 128;
        aRow = wm*64 + (lane & 15);
        aCol = (lane >> 4) << 3;
        bRow = wn*64 + (lane & 7) + ((lane & 16) >> 1);
        bCol = (lane & 8);
    }

    template<bool IN_SPLIT>
    __device__ __forceinline__ void load_tile(const __half* A, const __half* W,
                                              int K, int k0, int st) {
        const uint32_t abase = smem_base + (uint32_t)(st*STAGEH*2);
        const uint32_t wbase = abase + (uint32_t)(HTILE*2);
        #pragma unroll
        for (int i = 0; i < 8; i++) {
            int idx  = i*128 + tid;
            int row  = idx >> 3;
            int kc   = (idx & 7) << 3;
            const __half* srcA;
            if (IN_SPLIT) {
                int gm = bm + row, gk = k0 + kc;
                srcA = A + ((size_t)((gm >> 10)*HH + (gk >> 6)))*(SS*HDIM)
                         + (size_t)(gm & 1023)*HDIM + (gk & 63);
            } else {
                srcA = A + (size_t)(bm + row)*K + k0 + kc;
            }
            uint32_t dA = abase + (uint32_t)((row*HST + kc) * 2);
            asm volatile("cp.async.cg.shared.global [%0], [%1], 16;" :: "r"(dA), "l"(srcA));
            const __half* srcW = W + (size_t)(bn + row)*K + k0 + kc;
            uint32_t dW = wbase + (uint32_t)((row*HST + kc) * 2);
            asm volatile("cp.async.cg.shared.global [%0], [%1], 16;" :: "r"(dW), "l"(srcW));
        }
        asm volatile("cp.async.commit_group;");
    }

    __device__ __forceinline__ void frag_load(uint32_t abuf, uint32_t bbuf, int kh,
                                              uint32_t* fa, uint32_t* fb) {
        #pragma unroll
        for (int mi = 0; mi < 4; mi++)
            ldmx4(fa[mi*4+0], fa[mi*4+1], fa[mi*4+2], fa[mi*4+3],
                  abuf + (uint32_t)(((aRow + mi*16)*HST + kh + aCol) * 2));
        #pragma unroll
        for (int np = 0; np < 4; np++)
            ldmx4(fb[np*4+0], fb[np*4+1], fb[np*4+2], fb[np*4+3],
                  bbuf + (uint32_t)(((bRow + np*16)*HST + kh + bCol) * 2));
    }

    __device__ __forceinline__ void mma_all(float acc[4][8][4],
                                            const uint32_t* fa, const uint32_t* fb) {
        #pragma unroll
        for (int mi = 0; mi < 4; mi++)
            #pragma unroll
            for (int ni = 0; ni < 8; ni++) {
                const uint32_t* b = &fb[(ni >> 1)*4 + (ni & 1)*2];
                MMA_F16(acc[mi][ni],
                        fa[mi*4+0], fa[mi*4+1], fa[mi*4+2], fa[mi*4+3],
                        b[0], b[1]);
            }
    }

    __device__ __forceinline__ void compute(int st, float acc[4][8][4]) {
        const uint32_t abuf = smem_base + (uint32_t)(st*STAGEH*2);
        const uint32_t bbuf = abuf + (uint32_t)(HTILE*2);
        uint32_t fa[2][16], fb[2][16];
        frag_load(abuf, bbuf, 0, fa[0], fb[0]);
        #pragma unroll
        for (int ks = 0; ks < 4; ks++) {
            if (ks < 3)
                frag_load(abuf, bbuf, (ks+1)*16, fa[(ks+1) & 1], fb[(ks+1) & 1]);
            mma_all(acc, fa[ks & 1], fb[ks & 1]);
        }
    }
};

template<bool IN_SPLIT>
__device__ __forceinline__ void gemm_mainloop(GemmCore& g, const __half* A,
                                              const __half* W, int K,
                                              float acc[4][8][4]) {
    const int nt = K / GBK;   // 16
    g.load_tile<IN_SPLIT>(A, W, K, 0, 0);
    g.load_tile<IN_SPLIT>(A, W, K, GBK, 1);
    #pragma unroll 1
    for (int kt = 0; kt < nt; kt++) {
        if (kt < nt - 1) asm volatile("cp.async.wait_group 1;" ::: "memory");
        else             asm volatile("cp.async.wait_group 0;" ::: "memory");
        __syncthreads();
        if (kt + 2 < nt)
            g.load_tile<IN_SPLIT>(A, W, K, (kt+2)*GBK, (kt+2) % 3);
        g.compute(kt % 3, acc);
    }
}

// epilogue helpers ----------------------------------------------------------
__device__ __forceinline__ void epi_mode1(GemmCore& g, float acc[4][8][4],
                                          const float* bias, __half* C) {
    #pragma unroll
    for (int mi = 0; mi < 4; mi++)
        #pragma unroll
        for (int ni = 0; ni < 8; ni++) {
            int m = g.bm + g.wm*64 + mi*16 + g.lr;
            int n = g.bn + g.wn*64 + ni*8 + 2*g.lc;
            float2 bv = *(const float2*)(bias + n);
            float v00 = fmaxf(acc[mi][ni][0] + bv.x, 0.f);
            float v01 = fmaxf(acc[mi][ni][1] + bv.y, 0.f);
            float v10 = fmaxf(acc[mi][ni][2] + bv.x, 0.f);
            float v11 = fmaxf(acc[mi][ni][3] + bv.y, 0.f);
            size_t head = (size_t)((m >> 10)*HH + (n >> 6))*(SS*HDIM) + (n & 63);
            *(__half2*)(C + head + (size_t)( m    & 1023)*HDIM) = __floats2half2_rn(v00, v01);
            *(__half2*)(C + head + (size_t)((m+8) & 1023)*HDIM) = __floats2half2_rn(v10, v11);
        }
}

__device__ __forceinline__ void epi_mode2(GemmCore& g, float acc[4][8][4],
                                          const float* bias, __half* C) {
    #pragma unroll
    for (int mi = 0; mi < 4; mi++)
        #pragma unroll
        for (int ni = 0; ni < 8; ni++) {
            int m = g.bm + g.wm*64 + mi*16 + g.lr;
            int n = g.bn + g.wn*64 + ni*8 + 2*g.lc;
            float2 bv = *(const float2*)(bias + n);
            float v00 = fmaxf(acc[mi][ni][0] + bv.x, 0.f);
            float v01 = fmaxf(acc[mi][ni][1] + bv.y, 0.f);
            float v10 = fmaxf(acc[mi][ni][2] + bv.x, 0.f);
            float v11 = fmaxf(acc[mi][ni][3] + bv.y, 0.f);
            size_t head = (size_t)((m >> 10)*HH + (n >> 6))*(SS*HDIM);
            size_t drow0 = head + (size_t)(n & 63)*SS;
            size_t drow1 = head + (size_t)((n+1) & 63)*SS;
            C[drow0 + ( m    & 1023)] = __float2half_rn(v00);
            C[drow1 + ( m    & 1023)] = __float2half_rn(v01);
            C[drow0 + ((m+8) & 1023)] = __float2half_rn(v10);
            C[drow1 + ((m+8) & 1023)] = __float2half_rn(v11);
        }
}

// fused Q/K/V projection: blockIdx.z selects tensor; z==2 (V) stores transposed
__global__ void __launch_bounds__(128, 2) gemm_qkv(QKVArgs args) {
    extern __shared__ __half smh[];
    GemmCore g; g.init((uint32_t)__cvta_generic_to_shared(smh));
    const int z = blockIdx.z;

    float acc[4][8][4];
    #pragma unroll
    for (int mi = 0; mi < 4; mi++)
        #pragma unroll
        for (int ni = 0; ni < 8; ni++)
            #pragma unroll
            for (int r = 0; r < 4; r++) acc[mi][ni][r] = 0.f;

    gemm_mainloop<false>(g, args.A[z], args.W[z], DD, acc);

    if (z == 2) epi_mode2(g, acc, args.b[z], args.C[z]);
    else        epi_mode1(g, acc, args.b[z], args.C[z]);
}

// output projection: split-head fp16 in, fp32 row-major out
__global__ void __launch_bounds__(128, 2) gemm_out(
    const __half* __restrict__ A, const __half* __restrict__ W,
    const float* __restrict__ bias, float* __restrict__ C)
{
    extern __shared__ __half smh[];
    GemmCore g; g.init((uint32_t)__cvta_generic_to_shared(smh));

    float acc[4][8][4];
    #pragma unroll
    for (int mi = 0; mi < 4; mi++)
        #pragma unroll
        for (int ni = 0; ni < 8; ni++)
            #pragma unroll
            for (int r = 0; r < 4; r++) acc[mi][ni][r] = 0.f;

    gemm_mainloop<true>(g, A, W, DD, acc);

    #pragma unroll
    for (int mi = 0; mi < 4; mi++)
        #pragma unroll
        for (int ni = 0; ni < 8; ni++) {
            int m = g.bm + g.wm*64 + mi*16 + g.lr;
            int n = g.bn + g.wn*64 + ni*8 + 2*g.lc;
            float2 bv = *(const float2*)(bias + n);
            float2 r0, r1;
            r0.x = fmaxf(acc[mi][ni][0] + bv.x, 0.f);
            r0.y = fmaxf(acc[mi][ni][1] + bv.y, 0.f);
            r1.x = fmaxf(acc[mi][ni][2] + bv.x, 0.f);
            r1.y = fmaxf(acc[mi][ni][3] + bv.y, 0.f);
            *(float2*)(C + (size_t)m*DD + n)     = r0;
            *(float2*)(C + (size_t)(m+8)*DD + n) = r1;
        }
}

// ---------------------------------------------------------------------------
// Causal flash attention, fp16 mma + ldmatrix fragments (unchanged).
// ---------------------------------------------------------------------------
#define FTILE (64*HST)

__global__ void __launch_bounds__(128, 3) flash_attn_h(
    const __half* __restrict__ Q, const __half* __restrict__ K,
    const __half* __restrict__ V, __half* __restrict__ Y)
{
    extern __shared__ __half smh[];
    __half* Ps = smh + 4*FTILE;

    const int tid  = threadIdx.x;
    const int lane = tid & 31;
    const int warp = tid >> 5;
    const int lr   = lane >> 2;
    const int lc   = lane & 3;
    const int qt   = blockIdx.x;
    const int bh   = blockIdx.y;
    const int r0   = warp*16 + lr;

    const __half* Qb = Q + (size_t)bh*SS*HDIM + (size_t)qt*64*HDIM;
    const __half* Kb = K + (size_t)bh*SS*HDIM;
    const __half* Vb = V + (size_t)bh*SS*HDIM;   // [d][key]

    uint32_t smem_base = (uint32_t)__cvta_generic_to_shared(smh);
    const uint32_t psbase = smem_base + (uint32_t)(4*FTILE*2);

    const int aRow = warp*16 + (lane & 15);
    const int aCol = (lane >> 4) << 3;
    const int bRow = (lane & 7) + ((lane & 16) >> 1);
    const int bCol = (lane & 8);

    const __half2 scale = __floats2half2_rn(0.125f, 0.125f);
    #pragma unroll
    for (int i = 0; i < 4; i++) {
        int idx = tid + i*128;
        int row = idx >> 3;
        int c8  = (idx & 7) << 3;
        uint4 raw = *(const uint4*)(Qb + row*HDIM + c8);
        __half2* h = (__half2*)&raw;
        h[0] = __hmul2(h[0], scale); h[1] = __hmul2(h[1], scale);
        h[2] = __hmul2(h[2], scale); h[3] = __hmul2(h[3], scale);
        *(uint4*)&Ps[row*HST + c8] = raw;
    }
    __syncthreads();

    uint32_t qf[4][4];
    #pragma unroll
    for (int ks = 0; ks < 4; ks++)
        ldmx4(qf[ks][0], qf[ks][1], qf[ks][2], qf[ks][3],
              psbase + (uint32_t)((aRow*HST + ks*16 + aCol) * 2));

    auto load_kv = [&](int kt, int buf) {
        const __half* Kt = Kb + (size_t)kt*64*HDIM;
        const __half* Vt = Vb + (size_t)kt*64;
        #pragma unroll
        for (int i = 0; i < 4; i++) {
            int idx = tid + i*128;
            int row = idx >> 3;
            int c8  = (idx & 7) << 3;
            uint32_t dK = smem_base + (uint32_t)((buf*FTILE + row*HST + c8)*2);
            asm volatile("cp.async.cg.shared.global [%0], [%1], 16;"
                         :: "r"(dK), "l"(Kt + row*HDIM + c8));
            uint32_t dV = smem_base + (uint32_t)(((2 + buf)*FTILE + row*HST + c8)*2);
            asm volatile("cp.async.cg.shared.global [%0], [%1], 16;"
                         :: "r"(dV), "l"(Vt + (size_t)row*SS + c8));
        }
        asm volatile("cp.async.commit_group;");
    };

    load_kv(0, 0);

    float m0 = -1e30f, m1 = -1e30f, l0 = 0.f, l1 = 0.f;
    float o[8][4];
    #pragma unroll
    for (int ni = 0; ni < 8; ni++)
        #pragma unroll
        for (int r = 0; r < 4; r++) o[ni][r] = 0.f;

    for (int kt = 0; kt <= qt; kt++) {
        const int buf = kt & 1;
        asm volatile("cp.async.wait_group 0;");
        __syncthreads();
        if (kt < qt) load_kv(kt + 1, buf ^ 1);

        const uint32_t kbuf = smem_base + (uint32_t)((buf*FTILE)*2);
        const uint32_t vbuf = smem_base + (uint32_t)(((2 + buf)*FTILE)*2);

        float s[8][4];
        #pragma unroll
        for (int ni = 0; ni < 8; ni++)
            #pragma unroll
            for (int r = 0; r < 4; r++) s[ni][r] = 0.f;

        #pragma unroll
        for (int ks = 0; ks < 4; ks++) {
            int kh = ks*16;
            uint32_t b[8][2];
            #pragma unroll
            for (int np = 0; np < 4; np++)
                ldmx4(b[2*np][0], b[2*np][1], b[2*np+1][0], b[2*np+1][1],
                      kbuf + (uint32_t)(((bRow + np*16)*HST + kh + bCol) * 2));
            #pragma unroll
            for (int ni = 0; ni < 8; ni++)
                MMA_F16(s[ni], qf[ks][0], qf[ks][1], qf[ks][2], qf[ks][3],
                        b[ni][0], b[ni][1]);
        }

        if (kt == qt) {
            #pragma unroll
            for (int ni = 0; ni < 8; ni++) {
                int c = ni*8 + 2*lc;
                if (c     > r0    ) s[ni][0] = -1e9f;
                if (c + 1 > r0    ) s[ni][1] = -1e9f;
                if (c     > r0 + 8) s[ni][2] = -1e9f;
                if (c + 1 > r0 + 8) s[ni][3] = -1e9f;
            }
        }

        float mx0 = -1e30f, mx1 = -1e30f;
        #pragma unroll
        for (int ni = 0; ni < 8; ni++) {
            mx0 = fmaxf(mx0, fmaxf(s[ni][0], s[ni][1]));
            mx1 = fmaxf(mx1, fmaxf(s[ni][2], s[ni][3]));
        }
        mx0 = fmaxf(mx0, __shfl_xor_sync(0xffffffffu, mx0, 1));
        mx0 = fmaxf(mx0, __shfl_xor_sync(0xffffffffu, mx0, 2));
        mx1 = fmaxf(mx1, __shfl_xor_sync(0xffffffffu, mx1, 1));
        mx1 = fmaxf(mx1, __shfl_xor_sync(0xffffffffu, mx1, 2));

        float mn0 = fmaxf(m0, mx0), mn1 = fmaxf(m1, mx1);
        float c0 = __expf(m0 - mn0), c1 = __expf(m1 - mn1);
        float rs0 = 0.f, rs1 = 0.f;
        #pragma unroll
        for (int ni = 0; ni < 8; ni++) {
            s[ni][0] = __expf(s[ni][0] - mn0);
            s[ni][1] = __expf(s[ni][1] - mn0);
            s[ni][2] = __expf(s[ni][2] - mn1);
            s[ni][3] = __expf(s[ni][3] - mn1);
            rs0 += s[ni][0] + s[ni][1];
            rs1 += s[ni][2] + s[ni][3];
        }
        rs0 += __shfl_xor_sync(0xffffffffu, rs0, 1);
        rs0 += __shfl_xor_sync(0xffffffffu, rs0, 2);
        rs1 += __shfl_xor_sync(0xffffffffu, rs1, 1);
        rs1 += __shfl_xor_sync(0xffffffffu, rs1, 2);
        l0 = l0*c0 + rs0;  m0 = mn0;
        l1 = l1*c1 + rs1;  m1 = mn1;

        #pragma unroll
        for (int ni = 0; ni < 8; ni++) {
            o[ni][0] *= c0;  o[ni][1] *= c0;
            o[ni][2] *= c1;  o[ni][3] *= c1;
            *(__half2*)&Ps[ r0     *HST + ni*8 + 2*lc] = __floats2half2_rn(s[ni][0], s[ni][1]);
            *(__half2*)&Ps[(r0 + 8)*HST + ni*8 + 2*lc] = __floats2half2_rn(s[ni][2], s[ni][3]);
        }
        __syncwarp();

        #pragma unroll
        for (int ks = 0; ks < 4; ks++) {
            int kh = ks*16;
            uint32_t a0, a1, a2, a3;
            ldmx4(a0, a1, a2, a3, psbase + (uint32_t)((aRow*HST + kh + aCol) * 2));
            uint32_t b[8][2];
            #pragma unroll
            for (int np = 0; np < 4; np++)
                ldmx4(b[2*np][0], b[2*np][1], b[2*np+1][0], b[2*np+1][1],
                      vbuf + (uint32_t)(((bRow + np*16)*HST + kh + bCol) * 2));
            #pragma unroll
            for (int ni = 0; ni < 8; ni++)
                MMA_F16(o[ni], a0, a1, a2, a3, b[ni][0], b[ni][1]);
        }
    }

    float inv0 = 1.f / l0, inv1 = 1.f / l1;
    __half* Yb = Y + (size_t)bh*SS*HDIM + (size_t)qt*64*HDIM;
    #pragma unroll
    for (int ni = 0; ni < 8; ni++) {
        int c = ni*8 + 2*lc;
        *(__half2*)(Yb + (size_t) r0     *HDIM + c) = __floats2half2_rn(o[ni][0]*inv0, o[ni][1]*inv0);
        *(__half2*)(Yb + (size_t)(r0 + 8)*HDIM + c) = __floats2half2_rn(o[ni][2]*inv1, o[ni][3]*inv1);
    }
}

// ---------------------------------------------------------------------------
extern "C" void kernel_launch(void* const* d_in, const int* in_sizes, int n_in,
                              void* d_out, int out_size) {
    const float* q  = (const float*)d_in[0];
    const float* k  = (const float*)d_in[1];
    const float* v  = (const float*)d_in[2];
    // d_in[3] = mask (int32 tril) — causal structure implemented directly
    const float* bq = (const float*)d_in[5];
    const float* bk = (const float*)d_in[7];
    const float* bv = (const float*)d_in[9];
    const float* bo = (const float*)d_in[11];
    float* out = (float*)d_out;

    __half *q16, *k16, *v16, *wq16, *wk16, *wv16, *wo16, *qh16, *kh16, *vht16, *y16;
    cudaGetSymbolAddress((void**)&q16,  g_q16);
    cudaGetSymbolAddress((void**)&k16,  g_k16);
    cudaGetSymbolAddress((void**)&v16,  g_v16);
    cudaGetSymbolAddress((void**)&wq16, g_wq16);
    cudaGetSymbolAddress((void**)&wk16, g_wk16);
    cudaGetSymbolAddress((void**)&wv16, g_wv16);
    cudaGetSymbolAddress((void**)&wo16, g_wo16);
    cudaGetSymbolAddress((void**)&qh16, g_qh16);
    cudaGetSymbolAddress((void**)&kh16, g_kh16);
    cudaGetSymbolAddress((void**)&vht16, g_vht16);
    cudaGetSymbolAddress((void**)&y16,  g_y16);

    CvtArgs ca;
    ca.src[0] = q;                      ca.dst[0] = q16;  ca.n[0] = BB*SS*DD;
    ca.src[1] = k;                      ca.dst[1] = k16;  ca.n[1] = BB*SS*DD;
    ca.src[2] = v;                      ca.dst[2] = v16;  ca.n[2] = BB*SS*DD;
    ca.src[3] = (const float*)d_in[4];  ca.dst[3] = wq16; ca.n[3] = DD*DD;
    ca.src[4] = (const float*)d_in[6];  ca.dst[4] = wk16; ca.n[4] = DD*DD;
    ca.src[5] = (const float*)d_in[8];  ca.dst[5] = wv16; ca.n[5] = DD*DD;
    ca.src[6] = (const float*)d_in[10]; ca.dst[6] = wo16; ca.n[6] = DD*DD;
    convert_all<<<dim3(2048, 7), 256>>>(ca);

    cudaFuncSetAttribute(gemm_qkv, cudaFuncAttributeMaxDynamicSharedMemorySize, GEMM_SMEM);
    cudaFuncSetAttribute(gemm_out, cudaFuncAttributeMaxDynamicSharedMemorySize, GEMM_SMEM);

    QKVArgs qa;
    qa.A[0] = q16;  qa.W[0] = wq16; qa.b[0] = bq; qa.C[0] = qh16;
    qa.A[1] = k16;  qa.W[1] = wk16; qa.b[1] = bk; qa.C[1] = kh16;
    qa.A[2] = v16;  qa.W[2] = wv16; qa.b[2] = bv; qa.C[2] = vht16;

    dim3 qkvgrid(DD/128, (BB*SS)/128, 3);   // (8, 32, 3) = 768 CTAs
    gemm_qkv<<<qkvgrid, 128, GEMM_SMEM>>>(qa);

    const int flash_smem = 5 * FTILE * (int)sizeof(__half);  // 46080 B
    cudaFuncSetAttribute(flash_attn_h, cudaFuncAttributeMaxDynamicSharedMemorySize, flash_smem);
    flash_attn_h<<<dim3(SS/64, NBH), 128, flash_smem>>>(qh16, kh16, vht16, y16);

    dim3 ogrid(DD/128, (BB*SS)/128);        // (8, 32)
    gemm_out<<<ogrid, 128, GEMM_SMEM>>>(y16, wo16, bo, out);
}

// round 9
// speedup vs baseline: 1.0781x; 1.0781x over previous
#include <cuda_runtime.h>
#include <cuda_fp16.h>
#include <cstdint>

#define BB 4
#define SS 1024
#define DD 1024
#define HH 16
#define HDIM 64
#define NBH (BB*HH)

// fp16 scratch (allocation-free)
__device__ __align__(16) __half g_q16 [BB*SS*DD];
__device__ __align__(16) __half g_k16 [BB*SS*DD];
__device__ __align__(16) __half g_v16 [BB*SS*DD];
__device__ __align__(16) __half g_wq16[DD*DD];
__device__ __align__(16) __half g_wk16[DD*DD];
__device__ __align__(16) __half g_wv16[DD*DD];
__device__ __align__(16) __half g_wo16[DD*DD];
__device__ __align__(16) __half g_qh16[NBH*SS*HDIM];   // [bh][q][d]
__device__ __align__(16) __half g_kh16[NBH*SS*HDIM];   // [bh][key][d]
__device__ __align__(16) __half g_vht16[NBH*SS*HDIM];  // [bh][d][key]  TRANSPOSED
__device__ __align__(16) __half g_y16 [NBH*SS*HDIM];   // [bh][q][d]

#define MMA_F16(acc, a0,a1,a2,a3, b0,b1)                                    \
    asm volatile(                                                           \
        "mma.sync.aligned.m16n8k16.row.col.f32.f16.f16.f32 "                \
        "{%0,%1,%2,%3}, {%4,%5,%6,%7}, {%8,%9}, {%0,%1,%2,%3};"             \
        : "+f"(acc[0]), "+f"(acc[1]), "+f"(acc[2]), "+f"(acc[3])            \
        : "r"(a0), "r"(a1), "r"(a2), "r"(a3), "r"(b0), "r"(b1))

__device__ __forceinline__ void ldmx4(uint32_t& r0, uint32_t& r1,
                                      uint32_t& r2, uint32_t& r3, uint32_t addr) {
    asm volatile("ldmatrix.sync.aligned.m8n8.x4.shared.b16 {%0,%1,%2,%3}, [%4];"
                 : "=r"(r0), "=r"(r1), "=r"(r2), "=r"(r3) : "r"(addr));
}

// ---------------------------------------------------------------------------
// Fused fp32 -> fp16 conversion for 7 tensors in one launch.
// ---------------------------------------------------------------------------
struct CvtArgs {
    const float* src[7];
    __half*      dst[7];
    int          n[7];
};

__global__ void __launch_bounds__(256) convert_all(CvtArgs args) {
    const int t = blockIdx.y;
    const int n = args.n[t];
    int base = (blockIdx.x * 256 + threadIdx.x) * 8;
    if (base >= n) return;
    const float4* s = (const float4*)(args.src[t] + base);
    float4 f0 = s[0], f1 = s[1];
    __half2 h0 = __floats2half2_rn(f0.x, f0.y);
    __half2 h1 = __floats2half2_rn(f0.z, f0.w);
    __half2 h2 = __floats2half2_rn(f1.x, f1.y);
    __half2 h3 = __floats2half2_rn(f1.z, f1.w);
    uint4 o;
    o.x = *(uint32_t*)&h0; o.y = *(uint32_t*)&h1;
    o.z = *(uint32_t*)&h2; o.w = *(uint32_t*)&h3;
    *(uint4*)(args.dst[t] + base) = o;
}

// ---------------------------------------------------------------------------
// FP16 tensor-core GEMM + bias + ReLU (round-7 winner config).
// BM=BN=128, BK=64, 256 threads (8 warps 4x2), warp tile 32x64, m16n8k16.
// 3-stage cp.async pipeline, wait_group 1.
// ---------------------------------------------------------------------------
#define GBK 64
#define HST 72
#define HTILE (128*HST)
#define STAGEH (2*HTILE)
#define GEMM_SMEM (3*STAGEH*2)          // 110592 bytes

struct QKVArgs {
    const __half* A[3];
    const __half* W[3];
    const float*  b[3];
    __half*       C[3];
};

struct GemmCore {
    uint32_t smem_base;
    int tid, lane, warp, wm, wn, lr, lc, bm, bn;
    int aRow, aCol, bRow, bCol;

    __device__ __forceinline__ void init(uint32_t sb) {
        smem_base = sb;
        tid  = threadIdx.x;
        lane = tid & 31;
        warp = tid >> 5;
        wm   = warp & 3;
        wn   = warp >> 2;
        lr   = lane >> 2;
        lc   = lane & 3;
        bm   = blockIdx.y * 128;
        bn   = blockIdx.x * 128;
        aRow = wm*32 + (lane & 15);
        aCol = (lane >> 4) << 3;
        bRow = wn*64 + (lane & 7) + ((lane & 16) >> 1);
        bCol = (lane & 8);
    }

    template<bool IN_SPLIT>
    __device__ __forceinline__ void load_tile(const __half* A, const __half* W,
                                              int K, int k0, int st) {
        const uint32_t abase = smem_base + (uint32_t)(st*STAGEH*2);
        const uint32_t wbase = abase + (uint32_t)(HTILE*2);
        #pragma unroll
        for (int i = 0; i < 4; i++) {
            int idx  = i*256 + tid;
            int row  = idx >> 3;
            int kc   = (idx & 7) << 3;
            const __half* srcA;
            if (IN_SPLIT) {
                int gm = bm + row, gk = k0 + kc;
                srcA = A + ((size_t)((gm >> 10)*HH + (gk >> 6)))*(SS*HDIM)
                         + (size_t)(gm & 1023)*HDIM + (gk & 63);
            } else {
                srcA = A + (size_t)(bm + row)*K + k0 + kc;
            }
            uint32_t dA = abase + (uint32_t)((row*HST + kc) * 2);
            asm volatile("cp.async.cg.shared.global [%0], [%1], 16;" :: "r"(dA), "l"(srcA));
            const __half* srcW = W + (size_t)(bn + row)*K + k0 + kc;
            uint32_t dW = wbase + (uint32_t)((row*HST + kc) * 2);
            asm volatile("cp.async.cg.shared.global [%0], [%1], 16;" :: "r"(dW), "l"(srcW));
        }
        asm volatile("cp.async.commit_group;");
    }

    __device__ __forceinline__ void compute(int st, float acc[2][8][4]) {
        const uint32_t abuf = smem_base + (uint32_t)(st*STAGEH*2);
        const uint32_t bbuf = abuf + (uint32_t)(HTILE*2);
        #pragma unroll
        for (int ks = 0; ks < 4; ks++) {
            const int kh = ks*16;
            uint32_t a[2][4], b[8][2];
            #pragma unroll
            for (int mi = 0; mi < 2; mi++)
                ldmx4(a[mi][0], a[mi][1], a[mi][2], a[mi][3],
                      abuf + (uint32_t)(((aRow + mi*16)*HST + kh + aCol) * 2));
            #pragma unroll
            for (int np = 0; np < 4; np++)
                ldmx4(b[2*np][0], b[2*np][1], b[2*np+1][0], b[2*np+1][1],
                      bbuf + (uint32_t)(((bRow + np*16)*HST + kh + bCol) * 2));
            #pragma unroll
            for (int mi = 0; mi < 2; mi++)
                #pragma unroll
                for (int ni = 0; ni < 8; ni++)
                    MMA_F16(acc[mi][ni],
                            a[mi][0], a[mi][1], a[mi][2], a[mi][3],
                            b[ni][0], b[ni][1]);
        }
    }
};

template<bool IN_SPLIT>
__device__ __forceinline__ void gemm_mainloop(GemmCore& g, const __half* A,
                                              const __half* W, int K,
                                              float acc[2][8][4]) {
    const int nt = K / GBK;   // 16
    g.load_tile<IN_SPLIT>(A, W, K, 0, 0);
    g.load_tile<IN_SPLIT>(A, W, K, GBK, 1);
    #pragma unroll 1
    for (int kt = 0; kt < nt; kt++) {
        if (kt < nt - 1) asm volatile("cp.async.wait_group 1;" ::: "memory");
        else             asm volatile("cp.async.wait_group 0;" ::: "memory");
        __syncthreads();
        if (kt + 2 < nt)
            g.load_tile<IN_SPLIT>(A, W, K, (kt+2)*GBK, (kt+2) % 3);
        g.compute(kt % 3, acc);
    }
}

__device__ __forceinline__ void epi_mode1(GemmCore& g, float acc[2][8][4],
                                          const float* bias, __half* C) {
    #pragma unroll
    for (int mi = 0; mi < 2; mi++)
        #pragma unroll
        for (int ni = 0; ni < 8; ni++) {
            int m = g.bm + g.wm*32 + mi*16 + g.lr;
            int n = g.bn + g.wn*64 + ni*8 + 2*g.lc;
            float2 bv = *(const float2*)(bias + n);
            float v00 = fmaxf(acc[mi][ni][0] + bv.x, 0.f);
            float v01 = fmaxf(acc[mi][ni][1] + bv.y, 0.f);
            float v10 = fmaxf(acc[mi][ni][2] + bv.x, 0.f);
            float v11 = fmaxf(acc[mi][ni][3] + bv.y, 0.f);
            size_t head = (size_t)((m >> 10)*HH + (n >> 6))*(SS*HDIM) + (n & 63);
            *(__half2*)(C + head + (size_t)( m    & 1023)*HDIM) = __floats2half2_rn(v00, v01);
            *(__half2*)(C + head + (size_t)((m+8) & 1023)*HDIM) = __floats2half2_rn(v10, v11);
        }
}

__device__ __forceinline__ void epi_mode2(GemmCore& g, float acc[2][8][4],
                                          const float* bias, __half* C) {
    #pragma unroll
    for (int mi = 0; mi < 2; mi++)
        #pragma unroll
        for (int ni = 0; ni < 8; ni++) {
            int m = g.bm + g.wm*32 + mi*16 + g.lr;
            int n = g.bn + g.wn*64 + ni*8 + 2*g.lc;
            float2 bv = *(const float2*)(bias + n);
            float v00 = fmaxf(acc[mi][ni][0] + bv.x, 0.f);
            float v01 = fmaxf(acc[mi][ni][1] + bv.y, 0.f);
            float v10 = fmaxf(acc[mi][ni][2] + bv.x, 0.f);
            float v11 = fmaxf(acc[mi][ni][3] + bv.y, 0.f);
            size_t head = (size_t)((m >> 10)*HH + (n >> 6))*(SS*HDIM);
            size_t drow0 = head + (size_t)(n & 63)*SS;
            size_t drow1 = head + (size_t)((n+1) & 63)*SS;
            C[drow0 + ( m    & 1023)] = __float2half_rn(v00);
            C[drow1 + ( m    & 1023)] = __float2half_rn(v01);
            C[drow0 + ((m+8) & 1023)] = __float2half_rn(v10);
            C[drow1 + ((m+8) & 1023)] = __float2half_rn(v11);
        }
}

__global__ void __launch_bounds__(256, 2) gemm_qkv(QKVArgs args) {
    extern __shared__ __half smh[];
    GemmCore g; g.init((uint32_t)__cvta_generic_to_shared(smh));
    const int z = blockIdx.z;

    float acc[2][8][4];
    #pragma unroll
    for (int mi = 0; mi < 2; mi++)
        #pragma unroll
        for (int ni = 0; ni < 8; ni++)
            #pragma unroll
            for (int r = 0; r < 4; r++) acc[mi][ni][r] = 0.f;

    gemm_mainloop<false>(g, args.A[z], args.W[z], DD, acc);

    if (z == 2) epi_mode2(g, acc, args.b[z], args.C[z]);
    else        epi_mode1(g, acc, args.b[z], args.C[z]);
}

__global__ void __launch_bounds__(256, 2) gemm_out(
    const __half* __restrict__ A, const __half* __restrict__ W,
    const float* __restrict__ bias, float* __restrict__ C)
{
    extern __shared__ __half smh[];
    GemmCore g; g.init((uint32_t)__cvta_generic_to_shared(smh));

    float acc[2][8][4];
    #pragma unroll
    for (int mi = 0; mi < 2; mi++)
        #pragma unroll
        for (int ni = 0; ni < 8; ni++)
            #pragma unroll
            for (int r = 0; r < 4; r++) acc[mi][ni][r] = 0.f;

    gemm_mainloop<true>(g, A, W, DD, acc);

    #pragma unroll
    for (int mi = 0; mi < 2; mi++)
        #pragma unroll
        for (int ni = 0; ni < 8; ni++) {
            int m = g.bm + g.wm*32 + mi*16 + g.lr;
            int n = g.bn + g.wn*64 + ni*8 + 2*g.lc;
            float2 bv = *(const float2*)(bias + n);
            float2 r0, r1;
            r0.x = fmaxf(acc[mi][ni][0] + bv.x, 0.f);
            r0.y = fmaxf(acc[mi][ni][1] + bv.y, 0.f);
            r1.x = fmaxf(acc[mi][ni][2] + bv.x, 0.f);
            r1.y = fmaxf(acc[mi][ni][3] + bv.y, 0.f);
            *(float2*)(C + (size_t)m*DD + n)     = r0;
            *(float2*)(C + (size_t)(m+8)*DD + n) = r1;
        }
}

// ---------------------------------------------------------------------------
// Causal flash attention, fp16 mma + ldmatrix fragments.
// LPT scheduling: heavy q-tiles (large qt) launch first (qt = gy-1-by).
// Split K/V commit groups: QK waits only on K; V awaited after softmax.
// ---------------------------------------------------------------------------
#define FTILE (64*HST)

__global__ void __launch_bounds__(128, 3) flash_attn_h(
    const __half* __restrict__ Q, const __half* __restrict__ K,
    const __half* __restrict__ V, __half* __restrict__ Y)
{
    extern __shared__ __half smh[];
    __half* Ps = smh + 4*FTILE;

    const int tid  = threadIdx.x;
    const int lane = tid & 31;
    const int warp = tid >> 5;
    const int lr   = lane >> 2;
    const int lc   = lane & 3;
    const int qt   = (int)(gridDim.y - 1 - blockIdx.y);   // heavy tiles first
    const int bh   = blockIdx.x;
    const int r0   = warp*16 + lr;

    const __half* Qb = Q + (size_t)bh*SS*HDIM + (size_t)qt*64*HDIM;
    const __half* Kb = K + (size_t)bh*SS*HDIM;
    const __half* Vb = V + (size_t)bh*SS*HDIM;   // [d][key]

    uint32_t smem_base = (uint32_t)__cvta_generic_to_shared(smh);
    const uint32_t psbase = smem_base + (uint32_t)(4*FTILE*2);

    const int aRow = warp*16 + (lane & 15);
    const int aCol = (lane >> 4) << 3;
    const int bRow = (lane & 7) + ((lane & 16) >> 1);
    const int bCol = (lane & 8);

    const __half2 scale = __floats2half2_rn(0.125f, 0.125f);
    #pragma unroll
    for (int i = 0; i < 4; i++) {
        int idx = tid + i*128;
        int row = idx >> 3;
        int c8  = (idx & 7) << 3;
        uint4 raw = *(const uint4*)(Qb + row*HDIM + c8);
        __half2* h = (__half2*)&raw;
        h[0] = __hmul2(h[0], scale); h[1] = __hmul2(h[1], scale);
        h[2] = __hmul2(h[2], scale); h[3] = __hmul2(h[3], scale);
        *(uint4*)&Ps[row*HST + c8] = raw;
    }
    __syncthreads();

    uint32_t qf[4][4];
    #pragma unroll
    for (int ks = 0; ks < 4; ks++)
        ldmx4(qf[ks][0], qf[ks][1], qf[ks][2], qf[ks][3],
              psbase + (uint32_t)((aRow*HST + ks*16 + aCol) * 2));

    // K and V in SEPARATE commit groups
    auto load_k = [&](int kt, int buf) {
        const __half* Kt = Kb + (size_t)kt*64*HDIM;
        #pragma unroll
        for (int i = 0; i < 4; i++) {
            int idx = tid + i*128;
            int row = idx >> 3;
            int c8  = (idx & 7) << 3;
            uint32_t dK = smem_base + (uint32_t)((buf*FTILE + row*HST + c8)*2);
            asm volatile("cp.async.cg.shared.global [%0], [%1], 16;"
                         :: "r"(dK), "l"(Kt + row*HDIM + c8));
        }
        asm volatile("cp.async.commit_group;");
    };
    auto load_v = [&](int kt, int buf) {
        const __half* Vt = Vb + (size_t)kt*64;
        #pragma unroll
        for (int i = 0; i < 4; i++) {
            int idx = tid + i*128;
            int row = idx >> 3;
            int c8  = (idx & 7) << 3;
            uint32_t dV = smem_base + (uint32_t)(((2 + buf)*FTILE + row*HST + c8)*2);
            asm volatile("cp.async.cg.shared.global [%0], [%1], 16;"
                         :: "r"(dV), "l"(Vt + (size_t)row*SS + c8));
        }
        asm volatile("cp.async.commit_group;");
    };

    load_k(0, 0);
    load_v(0, 0);

    float m0 = -1e30f, m1 = -1e30f, l0 = 0.f, l1 = 0.f;
    float o[8][4];
    #pragma unroll
    for (int ni = 0; ni < 8; ni++)
        #pragma unroll
        for (int r = 0; r < 4; r++) o[ni][r] = 0.f;

    for (int kt = 0; kt <= qt; kt++) {
        const int buf = kt & 1;
        // K(kt) done; V(kt) may still be in flight
        asm volatile("cp.async.wait_group 1;" ::: "memory");
        __syncthreads();
        if (kt < qt) { load_k(kt + 1, buf ^ 1); load_v(kt + 1, buf ^ 1); }

        const uint32_t kbuf = smem_base + (uint32_t)((buf*FTILE)*2);
        const uint32_t vbuf = smem_base + (uint32_t)(((2 + buf)*FTILE)*2);

        // ---- S = Qs @ K^T ----
        float s[8][4];
        #pragma unroll
        for (int ni = 0; ni < 8; ni++)
            #pragma unroll
            for (int r = 0; r < 4; r++) s[ni][r] = 0.f;

        #pragma unroll
        for (int ks = 0; ks < 4; ks++) {
            int kh = ks*16;
            uint32_t b[8][2];
            #pragma unroll
            for (int np = 0; np < 4; np++)
                ldmx4(b[2*np][0], b[2*np][1], b[2*np+1][0], b[2*np+1][1],
                      kbuf + (uint32_t)(((bRow + np*16)*HST + kh + bCol) * 2));
            #pragma unroll
            for (int ni = 0; ni < 8; ni++)
                MMA_F16(s[ni], qf[ks][0], qf[ks][1], qf[ks][2], qf[ks][3],
                        b[ni][0], b[ni][1]);
        }

        if (kt == qt) {
            #pragma unroll
            for (int ni = 0; ni < 8; ni++) {
                int c = ni*8 + 2*lc;
                if (c     > r0    ) s[ni][0] = -1e9f;
                if (c + 1 > r0    ) s[ni][1] = -1e9f;
                if (c     > r0 + 8) s[ni][2] = -1e9f;
                if (c + 1 > r0 + 8) s[ni][3] = -1e9f;
            }
        }

        // ---- online softmax (V(kt) arriving underneath) ----
        float mx0 = -1e30f, mx1 = -1e30f;
        #pragma unroll
        for (int ni = 0; ni < 8; ni++) {
            mx0 = fmaxf(mx0, fmaxf(s[ni][0], s[ni][1]));
            mx1 = fmaxf(mx1, fmaxf(s[ni][2], s[ni][3]));
        }
        mx0 = fmaxf(mx0, __shfl_xor_sync(0xffffffffu, mx0, 1));
        mx0 = fmaxf(mx0, __shfl_xor_sync(0xffffffffu, mx0, 2));
        mx1 = fmaxf(mx1, __shfl_xor_sync(0xffffffffu, mx1, 1));
        mx1 = fmaxf(mx1, __shfl_xor_sync(0xffffffffu, mx1, 2));

        float mn0 = fmaxf(m0, mx0), mn1 = fmaxf(m1, mx1);
        float c0 = __expf(m0 - mn0), c1 = __expf(m1 - mn1);
        float rs0 = 0.f, rs1 = 0.f;
        #pragma unroll
        for (int ni = 0; ni < 8; ni++) {
            s[ni][0] = __expf(s[ni][0] - mn0);
            s[ni][1] = __expf(s[ni][1] - mn0);
            s[ni][2] = __expf(s[ni][2] - mn1);
            s[ni][3] = __expf(s[ni][3] - mn1);
            rs0 += s[ni][0] + s[ni][1];
            rs1 += s[ni][2] + s[ni][3];
        }
        rs0 += __shfl_xor_sync(0xffffffffu, rs0, 1);
        rs0 += __shfl_xor_sync(0xffffffffu, rs0, 2);
        rs1 += __shfl_xor_sync(0xffffffffu, rs1, 1);
        rs1 += __shfl_xor_sync(0xffffffffu, rs1, 2);
        l0 = l0*c0 + rs0;  m0 = mn0;
        l1 = l1*c1 + rs1;  m1 = mn1;

        #pragma unroll
        for (int ni = 0; ni < 8; ni++) {
            o[ni][0] *= c0;  o[ni][1] *= c0;
            o[ni][2] *= c1;  o[ni][3] *= c1;
            *(__half2*)&Ps[ r0     *HST + ni*8 + 2*lc] = __floats2half2_rn(s[ni][0], s[ni][1]);
            *(__half2*)&Ps[(r0 + 8)*HST + ni*8 + 2*lc] = __floats2half2_rn(s[ni][2], s[ni][3]);
        }
        __syncwarp();

        // V(kt) must be resident now (leave the 2 groups for kt+1 in flight)
        if (kt < qt) asm volatile("cp.async.wait_group 2;" ::: "memory");
        else         asm volatile("cp.async.wait_group 0;" ::: "memory");

        // ---- O += P @ V ----
        #pragma unroll
        for (int ks = 0; ks < 4; ks++) {
            int kh = ks*16;
            uint32_t a0, a1, a2, a3;
            ldmx4(a0, a1, a2, a3, psbase + (uint32_t)((aRow*HST + kh + aCol) * 2));
            uint32_t b[8][2];
            #pragma unroll
            for (int np = 0; np < 4; np++)
                ldmx4(b[2*np][0], b[2*np][1], b[2*np+1][0], b[2*np+1][1],
                      vbuf + (uint32_t)(((bRow + np*16)*HST + kh + bCol) * 2));
            #pragma unroll
            for (int ni = 0; ni < 8; ni++)
                MMA_F16(o[ni], a0, a1, a2, a3, b[ni][0], b[ni][1]);
        }
    }

    float inv0 = 1.f / l0, inv1 = 1.f / l1;
    __half* Yb = Y + (size_t)bh*SS*HDIM + (size_t)qt*64*HDIM;
    #pragma unroll
    for (int ni = 0; ni < 8; ni++) {
        int c = ni*8 + 2*lc;
        *(__half2*)(Yb + (size_t) r0     *HDIM + c) = __floats2half2_rn(o[ni][0]*inv0, o[ni][1]*inv0);
        *(__half2*)(Yb + (size_t)(r0 + 8)*HDIM + c) = __floats2half2_rn(o[ni][2]*inv1, o[ni][3]*inv1);
    }
}

// ---------------------------------------------------------------------------
extern "C" void kernel_launch(void* const* d_in, const int* in_sizes, int n_in,
                              void* d_out, int out_size) {
    const float* q  = (const float*)d_in[0];
    const float* k  = (const float*)d_in[1];
    const float* v  = (const float*)d_in[2];
    // d_in[3] = mask (int32 tril) — causal structure implemented directly
    const float* bq = (const float*)d_in[5];
    const float* bk = (const float*)d_in[7];
    const float* bv = (const float*)d_in[9];
    const float* bo = (const float*)d_in[11];
    float* out = (float*)d_out;

    __half *q16, *k16, *v16, *wq16, *wk16, *wv16, *wo16, *qh16, *kh16, *vht16, *y16;
    cudaGetSymbolAddress((void**)&q16,  g_q16);
    cudaGetSymbolAddress((void**)&k16,  g_k16);
    cudaGetSymbolAddress((void**)&v16,  g_v16);
    cudaGetSymbolAddress((void**)&wq16, g_wq16);
    cudaGetSymbolAddress((void**)&wk16, g_wk16);
    cudaGetSymbolAddress((void**)&wv16, g_wv16);
    cudaGetSymbolAddress((void**)&wo16, g_wo16);
    cudaGetSymbolAddress((void**)&qh16, g_qh16);
    cudaGetSymbolAddress((void**)&kh16, g_kh16);
    cudaGetSymbolAddress((void**)&vht16, g_vht16);
    cudaGetSymbolAddress((void**)&y16,  g_y16);

    CvtArgs ca;
    ca.src[0] = q;                      ca.dst[0] = q16;  ca.n[0] = BB*SS*DD;
    ca.src[1] = k;                      ca.dst[1] = k16;  ca.n[1] = BB*SS*DD;
    ca.src[2] = v;                      ca.dst[2] = v16;  ca.n[2] = BB*SS*DD;
    ca.src[3] = (const float*)d_in[4];  ca.dst[3] = wq16; ca.n[3] = DD*DD;
    ca.src[4] = (const float*)d_in[6];  ca.dst[4] = wk16; ca.n[4] = DD*DD;
    ca.src[5] = (const float*)d_in[8];  ca.dst[5] = wv16; ca.n[5] = DD*DD;
    ca.src[6] = (const float*)d_in[10]; ca.dst[6] = wo16; ca.n[6] = DD*DD;
    convert_all<<<dim3(2048, 7), 256>>>(ca);

    cudaFuncSetAttribute(gemm_qkv, cudaFuncAttributeMaxDynamicSharedMemorySize, GEMM_SMEM);
    cudaFuncSetAttribute(gemm_out, cudaFuncAttributeMaxDynamicSharedMemorySize, GEMM_SMEM);

    QKVArgs qa;
    qa.A[0] = q16;  qa.W[0] = wq16; qa.b[0] = bq; qa.C[0] = qh16;
    qa.A[1] = k16;  qa.W[1] = wk16; qa.b[1] = bk; qa.C[1] = kh16;
    qa.A[2] = v16;  qa.W[2] = wv16; qa.b[2] = bv; qa.C[2] = vht16;

    dim3 qkvgrid(DD/128, (BB*SS)/128, 3);   // (8, 32, 3) = 768 CTAs
    gemm_qkv<<<qkvgrid, 256, GEMM_SMEM>>>(qa);

    const int flash_smem = 5 * FTILE * (int)sizeof(__half);  // 46080 B
    cudaFuncSetAttribute(flash_attn_h, cudaFuncAttributeMaxDynamicSharedMemorySize, flash_smem);
    flash_attn_h<<<dim3(NBH, SS/64), 128, flash_smem>>>(qh16, kh16, vht16, y16);

    dim3 ogrid(DD/128, (BB*SS)/128);        // (8, 32)
    gemm_out<<<ogrid, 256, GEMM_SMEM>>>(y16, wo16, bo, out);
}